// round 5
// baseline (speedup 1.0000x reference)
#include <cuda_runtime.h>

#define H  2048
#define S  8192
#define NB 296              // 2 blocks per SM on 148 SMs (152 available) -> all resident
#define NT 256

// Scratch (no allocs allowed). g_u starts zero (static init); block 0 re-zeros
// it at the end of every invocation, so "g_u == 0 on entry" holds for the
// correctness run, the capture, and every graph replay.
__device__ float    g_u[H];
__device__ float    g_mb[NB];
__device__ float    g_zb[NB];
__device__ unsigned g_count = 0;   // barrier arrival counter (self-resetting)
__device__ unsigned g_gen   = 0;   // barrier generation (monotonic across replays)

// Software grid barrier. Safe: all NB=296 blocks resident (2/SM enforced by
// __launch_bounds__(256,2): 128 regs/thr, ~8.3KB smem/block). Monotonic
// generation counter -> graph-replay safe.
__device__ __forceinline__ void grid_barrier() {
    __syncthreads();
    __threadfence();
    if (threadIdx.x == 0) {
        unsigned gen0 = *(volatile unsigned*)&g_gen;
        if (atomicAdd(&g_count, 1u) == NB - 1) {
            g_count = 0;
            __threadfence();
            atomicAdd(&g_gen, 1u);         // release
        } else {
            while (*(volatile unsigned*)&g_gen == gen0) { }
        }
        __threadfence();                   // acquire
    }
    __syncthreads();
}

__global__ __launch_bounds__(NT, 2)
void fused_attn(const float* __restrict__ hidden,
                const float* __restrict__ enc,
                const float* __restrict__ W,
                float* __restrict__ out) {
    const int b    = blockIdx.x;
    const int tid  = threadIdx.x;
    const int lane = tid & 31;
    const int wid  = tid >> 5;

    __shared__ float sU[H];        // staged u (8 KB)
    __shared__ float sE[28];       // this block's energies
    __shared__ float sM, sInvZ;

    // ---------------- Phase 1: u[j] = sum_i h[i] * W[i,j] ----------------
    // Block tile: j-strip (b&7)*256 + tid, i-strip of 56 rows. Fully unrolled
    // -> deep MLP within the 128-reg budget. Coalesced on j.
    {
        const int j  = ((b & 7) << 8) + tid;
        const int i0 = (b >> 3) * 56;          // 37 strips * 56 = 2072 >= 2048
        float acc = 0.0f;
#pragma unroll
        for (int r = 0; r < 56; ++r) {
            const int i = i0 + r;
            if (i < H)
                acc = fmaf(__ldg(hidden + i), W[(size_t)i * H + j], acc);
        }
        atomicAdd(&g_u[j], acc);
    }

    grid_barrier();   // g_u complete

    // Stage u into shared memory (L2-hot after phase 1).
#pragma unroll
    for (int r = 0; r < H / NT; ++r)
        sU[tid + r * NT] = g_u[tid + r * NT];
    __syncthreads();

    // ---------------- Phase 2: energies + block-local (m, z) -------------
    // Block b handles rows s = b + k*NB (k = 0..nrows-1, nrows = 27 or 28).
    // One warp per row (warps cycle k += 8); enc from global (L2-resident on
    // warm replays), u from smem. 16 independent float4 loads per row.
    const int nrows = (S - 1 - b) / NB + 1;
    const float4* uv = reinterpret_cast<const float4*>(sU);

    for (int k = wid; k < nrows; k += 8) {
        const int s = b + k * NB;
        const float4* row = reinterpret_cast<const float4*>(enc + (size_t)s * H);
        float acc = 0.0f;
#pragma unroll
        for (int t = 0; t < (H / 4) / 32; ++t) {   // 16 iterations
            float4 v = row[lane + t * 32];
            float4 u = uv [lane + t * 32];
            acc = fmaf(v.x, u.x, acc);
            acc = fmaf(v.y, u.y, acc);
            acc = fmaf(v.z, u.z, acc);
            acc = fmaf(v.w, u.w, acc);
        }
#pragma unroll
        for (int off = 16; off; off >>= 1)
            acc += __shfl_xor_sync(0xFFFFFFFFu, acc, off);
        if (lane == 0) sE[k] = acc;
    }
    __syncthreads();

    if (wid == 0) {
        const float v0 = (lane < nrows) ? sE[lane] : -1e30f;   // nrows <= 28
        float m = v0;
#pragma unroll
        for (int off = 16; off; off >>= 1)
            m = fmaxf(m, __shfl_xor_sync(0xFFFFFFFFu, m, off));
        float z = (lane < nrows) ? __expf(v0 - m) : 0.0f;
#pragma unroll
        for (int off = 16; off; off >>= 1)
            z += __shfl_xor_sync(0xFFFFFFFFu, z, off);
        if (lane == 0) { g_mb[b] = m; g_zb[b] = z; }
    }

    grid_barrier();   // all (m_b, z_b) visible

    // ---------------- Phase 3: global (M, 1/Z), redundant per block ------
    if (wid == 0) {
        float m = -1e30f;
        for (int i = lane; i < NB; i += 32) m = fmaxf(m, g_mb[i]);
#pragma unroll
        for (int off = 16; off; off >>= 1)
            m = fmaxf(m, __shfl_xor_sync(0xFFFFFFFFu, m, off));
        float z = 0.0f;
        for (int i = lane; i < NB; i += 32) z += g_zb[i] * __expf(g_mb[i] - m);
#pragma unroll
        for (int off = 16; off; off >>= 1)
            z += __shfl_xor_sync(0xFFFFFFFFu, z, off);
        if (lane == 0) { sM = m; sInvZ = 1.0f / z; }
    }
    __syncthreads();

    // ---------------- Phase 4: write softmax, restore g_u invariant ------
    if (tid < nrows)
        out[b + tid * NB] = __expf(sE[tid] - sM) * sInvZ;

    if (b == 0) {                  // all phase-2 g_u readers passed barrier 2
#pragma unroll
        for (int r = 0; r < H / NT; ++r)
            g_u[tid + r * NT] = 0.0f;
    }
}

// ---------------------------------------------------------------------------
// Launch. Inputs: hidden[2048], encoder_outputs[8192*2048], W[2048*2048],
// b[2048] (zero + softmax-invariant -> ignored). Output: 8192 floats.
// ---------------------------------------------------------------------------
extern "C" void kernel_launch(void* const* d_in, const int* in_sizes, int n_in,
                              void* d_out, int out_size) {
    const float* hidden = (const float*)d_in[0];
    const float* enc    = (const float*)d_in[1];
    const float* W      = (const float*)d_in[2];
    float* out          = (float*)d_out;

    fused_attn<<<NB, NT>>>(hidden, enc, W, out);
}

// round 6
// speedup vs baseline: 1.9403x; 1.9403x over previous
#include <cuda_runtime.h>

#define H 2048
#define S 8192

// Scratch (no allocs allowed). g_u starts zero (static init); k_finalize
// re-zeros it each invocation, so "g_u == 0 on entry" holds on every call.
__device__ float g_u[H];
__device__ float g_energy[S];
__device__ float g_mb[S / 8];     // per-energy-block local max   (1024)
__device__ float g_zb[S / 8];     // per-energy-block exp-sum     (1024)

// ---------------------------------------------------------------------------
// Kernel 1: u[j] += sum over an i-chunk of h[i] * W[i, j]   (W row-major)
// Grid (H/256, ICHUNKS) = (8, 16) = 128 blocks. Coalesced on j. atomicAdd
// partials into pre-zeroed g_u.
// ---------------------------------------------------------------------------
#define ICHUNKS 16
#define IROWS   (H / ICHUNKS)     // 128

__global__ void k_compute_u(const float* __restrict__ h,
                            const float* __restrict__ W) {
    int j  = blockIdx.x * blockDim.x + threadIdx.x;
    int i0 = blockIdx.y * IROWS;

    float acc = 0.0f;
#pragma unroll 8
    for (int i = i0; i < i0 + IROWS; ++i) {
        acc = fmaf(h[i], W[(size_t)i * H + j], acc);
    }
    atomicAdd(&g_u[j], acc);
}

// ---------------------------------------------------------------------------
// Kernel 2: energy[s] = enc[s,:] . u  — one warp per row, 8 rows per block.
// Each block also emits (m_b, z_b) = (local max, sum exp(e - m_b)).
// ---------------------------------------------------------------------------
__global__ void k_energy(const float* __restrict__ enc) {
    __shared__ float sE[8];

    int wid  = threadIdx.x >> 5;
    int lane = threadIdx.x & 31;
    int s    = blockIdx.x * 8 + wid;

    const float4* row = reinterpret_cast<const float4*>(enc + (size_t)s * H);
    const float4* uv  = reinterpret_cast<const float4*>(g_u);

    float acc = 0.0f;
#pragma unroll
    for (int k = 0; k < (H / 4) / 32; ++k) {   // 16 iterations
        float4 v = row[lane + k * 32];
        float4 u = uv[lane + k * 32];
        acc = fmaf(v.x, u.x, acc);
        acc = fmaf(v.y, u.y, acc);
        acc = fmaf(v.z, u.z, acc);
        acc = fmaf(v.w, u.w, acc);
    }
#pragma unroll
    for (int off = 16; off; off >>= 1)
        acc += __shfl_xor_sync(0xFFFFFFFFu, acc, off);

    if (lane == 0) {
        g_energy[s] = acc;
        sE[wid] = acc;
    }
    __syncthreads();

    if (threadIdx.x == 0) {
        float m = sE[0];
#pragma unroll
        for (int k = 1; k < 8; ++k) m = fmaxf(m, sE[k]);
        float z = 0.0f;
#pragma unroll
        for (int k = 0; k < 8; ++k) z += __expf(sE[k] - m);
        g_mb[blockIdx.x] = m;
        g_zb[blockIdx.x] = z;
    }
}

// ---------------------------------------------------------------------------
// Kernel 3: finalize. 32 blocks x 256 threads. Every block redundantly
// reduces the 1024 (m,z) pairs (L2-hot) to (M, 1/Z), then normalizes its
// own 256-row output slice. Blocks 0..7 also re-zero g_u.
// ---------------------------------------------------------------------------
__global__ void k_finalize(float* __restrict__ out) {
    __shared__ float red[8];
    __shared__ float sM, sInvZ;

    const int tid  = threadIdx.x;     // 0..255
    const int lane = tid & 31;
    const int wid  = tid >> 5;        // 0..7

    // Each thread owns 4 (m,z) pairs.
    float m0[4], z0[4];
#pragma unroll
    for (int k = 0; k < 4; ++k) {
        m0[k] = g_mb[tid + k * 256];
        z0[k] = g_zb[tid + k * 256];
    }

    // ---- block max ----
    float m = fmaxf(fmaxf(m0[0], m0[1]), fmaxf(m0[2], m0[3]));
#pragma unroll
    for (int off = 16; off; off >>= 1)
        m = fmaxf(m, __shfl_xor_sync(0xFFFFFFFFu, m, off));
    if (lane == 0) red[wid] = m;
    __syncthreads();
    if (tid < 8) {
        float v = red[tid];
#pragma unroll
        for (int off = 4; off; off >>= 1)
            v = fmaxf(v, __shfl_xor_sync(0xFFu, v, off));
        if (tid == 0) sM = v;
    }
    __syncthreads();
    const float M = sM;

    // ---- block sum of z_i * exp(m_i - M) ----
    float z = 0.0f;
#pragma unroll
    for (int k = 0; k < 4; ++k) z += z0[k] * __expf(m0[k] - M);
#pragma unroll
    for (int off = 16; off; off >>= 1)
        z += __shfl_xor_sync(0xFFFFFFFFu, z, off);
    if (lane == 0) red[wid] = z;
    __syncthreads();
    if (tid < 8) {
        float v = red[tid];
#pragma unroll
        for (int off = 4; off; off >>= 1)
            v += __shfl_xor_sync(0xFFu, v, off);
        if (tid == 0) sInvZ = 1.0f / v;
    }
    __syncthreads();
    const float invZ = sInvZ;

    // ---- normalize this block's slice ----
    const int s = blockIdx.x * 256 + tid;
    out[s] = __expf(g_energy[s] - M) * invZ;

    // ---- restore g_u == 0 invariant for the next invocation ----
    if (blockIdx.x < 8)
        g_u[blockIdx.x * 256 + tid] = 0.0f;
}

// ---------------------------------------------------------------------------
// Launch. Inputs: hidden[2048], encoder_outputs[8192*2048], W[2048*2048],
// b[2048] (zero + softmax-invariant -> ignored). Output: 8192 floats.
// ---------------------------------------------------------------------------
extern "C" void kernel_launch(void* const* d_in, const int* in_sizes, int n_in,
                              void* d_out, int out_size) {
    const float* hidden = (const float*)d_in[0];
    const float* enc    = (const float*)d_in[1];
    const float* W      = (const float*)d_in[2];
    float* out          = (float*)d_out;

    dim3 g1(H / 256, ICHUNKS);
    k_compute_u<<<g1, 256>>>(hidden, W);

    k_energy<<<S / 8, 256>>>(enc);

    k_finalize<<<S / 256, 256>>>(out);
}

// round 7
// speedup vs baseline: 1.9697x; 1.0152x over previous
#include <cuda_runtime.h>

#define H 2048
#define S 8192

// Scratch (no allocs allowed). g_u starts zero (static init); k_finalize
// re-zeros it each invocation, so "g_u == 0 on entry" holds on every call.
__device__ float g_u[H];
__device__ float g_energy[S];
__device__ float g_mb[S / 8];     // per-energy-block local max   (1024)
__device__ float g_zb[S / 8];     // per-energy-block exp-sum     (1024)

// ---------------------------------------------------------------------------
// Kernel 1: u[j] += sum over a 32-row i-chunk of h[i] * W[i, j]
// Grid (H/256, 64) = 512 blocks (~3.5/SM). Fully unrolled 32-row loop ->
// ~32 independent loads in flight per thread. Coalesced on j. atomicAdd
// partials into pre-zeroed g_u (512 adds per address, spread over 2048).
// ---------------------------------------------------------------------------
#define ICHUNKS 64
#define IROWS   (H / ICHUNKS)     // 32

__global__ void k_compute_u(const float* __restrict__ h,
                            const float* __restrict__ W) {
    const int j  = blockIdx.x * blockDim.x + threadIdx.x;
    const int i0 = blockIdx.y * IROWS;

    float acc = 0.0f;
#pragma unroll
    for (int r = 0; r < IROWS; ++r) {
        const int i = i0 + r;
        acc = fmaf(__ldg(h + i), W[(size_t)i * H + j], acc);
    }
    atomicAdd(&g_u[j], acc);
}

// ---------------------------------------------------------------------------
// Kernel 2: energy[s] = enc[s,:] . u  — one warp per row, 8 rows per block.
// Each block also emits (m_b, z_b) = (local max, sum exp(e - m_b)).
// ---------------------------------------------------------------------------
__global__ void k_energy(const float* __restrict__ enc) {
    __shared__ float sE[8];

    int wid  = threadIdx.x >> 5;
    int lane = threadIdx.x & 31;
    int s    = blockIdx.x * 8 + wid;

    const float4* row = reinterpret_cast<const float4*>(enc + (size_t)s * H);
    const float4* uv  = reinterpret_cast<const float4*>(g_u);

    float acc = 0.0f;
#pragma unroll
    for (int k = 0; k < (H / 4) / 32; ++k) {   // 16 iterations
        float4 v = row[lane + k * 32];
        float4 u = uv[lane + k * 32];
        acc = fmaf(v.x, u.x, acc);
        acc = fmaf(v.y, u.y, acc);
        acc = fmaf(v.z, u.z, acc);
        acc = fmaf(v.w, u.w, acc);
    }
#pragma unroll
    for (int off = 16; off; off >>= 1)
        acc += __shfl_xor_sync(0xFFFFFFFFu, acc, off);

    if (lane == 0) {
        g_energy[s] = acc;
        sE[wid] = acc;
    }
    __syncthreads();

    if (threadIdx.x == 0) {
        float m = sE[0];
#pragma unroll
        for (int k = 1; k < 8; ++k) m = fmaxf(m, sE[k]);
        float z = 0.0f;
#pragma unroll
        for (int k = 0; k < 8; ++k) z += __expf(sE[k] - m);
        g_mb[blockIdx.x] = m;
        g_zb[blockIdx.x] = z;
    }
}

// ---------------------------------------------------------------------------
// Kernel 3: finalize. 32 blocks x 256 threads. Every block redundantly
// reduces the 1024 (m,z) pairs (L2-hot) to (M, 1/Z), then normalizes its
// own 256-row output slice. Blocks 0..7 also re-zero g_u.
// ---------------------------------------------------------------------------
__global__ void k_finalize(float* __restrict__ out) {
    __shared__ float red[8];
    __shared__ float sM, sInvZ;

    const int tid  = threadIdx.x;     // 0..255
    const int lane = tid & 31;
    const int wid  = tid >> 5;        // 0..7

    float m0[4], z0[4];
#pragma unroll
    for (int k = 0; k < 4; ++k) {
        m0[k] = g_mb[tid + k * 256];
        z0[k] = g_zb[tid + k * 256];
    }

    // ---- block max ----
    float m = fmaxf(fmaxf(m0[0], m0[1]), fmaxf(m0[2], m0[3]));
#pragma unroll
    for (int off = 16; off; off >>= 1)
        m = fmaxf(m, __shfl_xor_sync(0xFFFFFFFFu, m, off));
    if (lane == 0) red[wid] = m;
    __syncthreads();
    if (tid < 8) {
        float v = red[tid];
#pragma unroll
        for (int off = 4; off; off >>= 1)
            v = fmaxf(v, __shfl_xor_sync(0xFFu, v, off));
        if (tid == 0) sM = v;
    }
    __syncthreads();
    const float M = sM;

    // ---- block sum of z_i * exp(m_i - M) ----
    float z = 0.0f;
#pragma unroll
    for (int k = 0; k < 4; ++k) z += z0[k] * __expf(m0[k] - M);
#pragma unroll
    for (int off = 16; off; off >>= 1)
        z += __shfl_xor_sync(0xFFFFFFFFu, z, off);
    if (lane == 0) red[wid] = z;
    __syncthreads();
    if (tid < 8) {
        float v = red[tid];
#pragma unroll
        for (int off = 4; off; off >>= 1)
            v += __shfl_xor_sync(0xFFu, v, off);
        if (tid == 0) sInvZ = 1.0f / v;
    }
    __syncthreads();
    const float invZ = sInvZ;

    // ---- normalize this block's slice ----
    const int s = blockIdx.x * 256 + tid;
    out[s] = __expf(g_energy[s] - M) * invZ;

    // ---- restore g_u == 0 invariant for the next invocation ----
    if (blockIdx.x < 8)
        g_u[blockIdx.x * 256 + tid] = 0.0f;
}

// ---------------------------------------------------------------------------
// Launch. Inputs: hidden[2048], encoder_outputs[8192*2048], W[2048*2048],
// b[2048] (zero + softmax-invariant -> ignored). Output: 8192 floats.
// ---------------------------------------------------------------------------
extern "C" void kernel_launch(void* const* d_in, const int* in_sizes, int n_in,
                              void* d_out, int out_size) {
    const float* hidden = (const float*)d_in[0];
    const float* enc    = (const float*)d_in[1];
    const float* W      = (const float*)d_in[2];
    float* out          = (float*)d_out;

    dim3 g1(H / 256, ICHUNKS);
    k_compute_u<<<g1, 256>>>(hidden, W);

    k_energy<<<S / 8, 256>>>(enc);

    k_finalize<<<S / 256, 256>>>(out);
}